// round 13
// baseline (speedup 1.0000x reference)
#include <cuda_runtime.h>
#include <cuda_bf16.h>
#include <math.h>
#include <cstdint>

// ---------------- problem constants ----------------
#define NIMG   2
#define S_PER  512
#define R_TOT  1024
#define C_FEAT 512
#define HW     2500
#define D_FEAT 25088
#define HIDN   1024
#define NCLS   21
#define DETN   100
#define CANDS  10240
#define NHEAD  128
#define LOG_MAX_F 4.135166556742356f

// ---------------- scratch ----------------
__device__ float          g_featT[NIMG * HW * C_FEAT];
__device__ __nv_bfloat16  g_Ahi[(size_t)R_TOT * D_FEAT];
__device__ __nv_bfloat16  g_Alo[(size_t)R_TOT * D_FEAT];
__device__ __nv_bfloat16  g_Bhi[(size_t)HIDN * D_FEAT];
__device__ __nv_bfloat16  g_Blo[(size_t)HIDN * D_FEAT];
__device__ __nv_bfloat16  g_h1hi[R_TOT * HIDN];
__device__ __nv_bfloat16  g_h1lo[R_TOT * HIDN];
__device__ __nv_bfloat16  g_w2Thi[HIDN * HIDN];
__device__ __nv_bfloat16  g_w2Tlo[HIDN * HIDN];
__device__ __nv_bfloat16  g_h2hi[R_TOT * HIDN];
__device__ __nv_bfloat16  g_h2lo[R_TOT * HIDN];
__device__ __nv_bfloat16  g_wcbhi[NHEAD * HIDN];
__device__ __nv_bfloat16  g_wcblo[NHEAD * HIDN];
__device__ float          g_bcb[NHEAD];
__device__ float          g_logits[R_TOT * NHEAD];
__device__ float          g_scores[R_TOT * NCLS];
__device__ float4         g_boxes4[R_TOT * NCLS];
__device__ int            g_map[NIMG * CANDS];

// ---------------- helpers ----------------
__device__ __forceinline__ uint32_t smem_u32(const void* p) {
    uint32_t a;
    asm("{ .reg .u64 t; cvta.to.shared.u64 t, %1; cvt.u32.u64 %0, t; }" : "=r"(a) : "l"(p));
    return a;
}
__device__ __forceinline__ float read_img(const void* p) {
    int iv = *(const int*)p;
    if (iv > 0 && iv < 1000000) return (float)iv;
    float fv = *(const float*)p;
    if (fv >= 1.0f && fv <= 1.0e6f) return fv;
    double dv = *(const double*)p;
    return (float)dv;
}

#define LDSM4(r, a) \
    asm volatile("ldmatrix.sync.aligned.m8n8.x4.shared.b16 {%0,%1,%2,%3}, [%4];" \
        : "=r"((r)[0]), "=r"((r)[1]), "=r"((r)[2]), "=r"((r)[3]) : "r"(a))

#define MMA_BF16(c, a, b0, b1) \
    asm volatile("mma.sync.aligned.m16n8k16.row.col.f32.bf16.bf16.f32 " \
        "{%0,%1,%2,%3},{%4,%5,%6,%7},{%8,%9},{%0,%1,%2,%3};" \
        : "+f"((c)[0]), "+f"((c)[1]), "+f"((c)[2]), "+f"((c)[3]) \
        : "r"((a)[0]), "r"((a)[1]), "r"((a)[2]), "r"((a)[3]), "r"(b0), "r"(b1))

#define CP16(dst, src) \
    asm volatile("cp.async.cg.shared.global [%0], [%1], 16;" :: "r"(dst), "l"(src))
#define CP_COMMIT() asm volatile("cp.async.commit_group;" ::: "memory")
#define CP_WAIT2()  asm volatile("cp.async.wait_group 2;" ::: "memory")

// ---------------- 1) transpose features [N,C,H,W] -> [N,H,W,C] ----------------
__global__ void transpose_feat(const float* __restrict__ in) {
    __shared__ float tile[32][33];
    int n  = blockIdx.z;
    int p0 = blockIdx.x * 32;
    int c0 = blockIdx.y * 32;
    int tx = threadIdx.x, ty = threadIdx.y;
    int p = p0 + tx, c = c0 + ty;
    if (p < HW) tile[ty][tx] = in[((size_t)(n * C_FEAT + c)) * HW + p];
    __syncthreads();
    p = p0 + ty; c = c0 + tx;
    if (p < HW) g_featT[((size_t)(n * HW + p)) * C_FEAT + c] = tile[tx][ty];
}

// ---------------- 2) ROI align v2: one block per roi (roi offset param) ------
__device__ __forceinline__ void split_store4(float v0, float v1, float v2, float v3, size_t base) {
    __nv_bfloat16 h0 = __float2bfloat16(v0), h1 = __float2bfloat16(v1),
                  h2 = __float2bfloat16(v2), h3 = __float2bfloat16(v3);
    float l0 = v0 - __bfloat162float(h0), l1 = v1 - __bfloat162float(h1),
          l2 = v2 - __bfloat162float(h2), l3 = v3 - __bfloat162float(h3);
    __nv_bfloat16 g0 = __float2bfloat16(l0), g1 = __float2bfloat16(l1),
                  g2 = __float2bfloat16(l2), g3 = __float2bfloat16(l3);
    uint2 uh, ul;
    uh.x = (uint32_t)__bfloat16_as_ushort(h0) | ((uint32_t)__bfloat16_as_ushort(h1) << 16);
    uh.y = (uint32_t)__bfloat16_as_ushort(h2) | ((uint32_t)__bfloat16_as_ushort(h3) << 16);
    ul.x = (uint32_t)__bfloat16_as_ushort(g0) | ((uint32_t)__bfloat16_as_ushort(g1) << 16);
    ul.y = (uint32_t)__bfloat16_as_ushort(g2) | ((uint32_t)__bfloat16_as_ushort(g3) << 16);
    *(uint2*)(g_Ahi + base) = uh;
    *(uint2*)(g_Alo + base) = ul;
}

__global__ __launch_bounds__(256) void roi_align2(const float* __restrict__ props, int r0) {
    __shared__ float4 sw4[196];
    __shared__ int4   so4[196];
    int r   = r0 + blockIdx.x;
    int n   = r >> 9;
    int tid = threadIdx.x;

    const float SCALE = 1.0f / 16.0f;
    float b0 = props[r*4+0] * SCALE;
    float b1 = props[r*4+1] * SCALE;
    float b2 = props[r*4+2] * SCALE;
    float b3 = props[r*4+3] * SCALE;
    float rw = fmaxf(b2 - b0, 1.0f);
    float rh = fmaxf(b3 - b1, 1.0f);
    float bw = rw * (1.0f / 7.0f);
    float bh = rh * (1.0f / 7.0f);

    if (tid < 196) {
        int pos = tid >> 2;
        int samp = tid & 3;
        int oy = pos / 7, ox = pos % 7;
        int sy = samp >> 1, sx = samp & 1;
        float gy = (float)oy + (sy ? 0.75f : 0.25f);
        float gx = (float)ox + (sx ? 0.75f : 0.25f);
        float y = b1 + gy * bh;
        float x = b0 + gx * bw;
        bool v = (y > -1.0f) && (y < 50.0f) && (x > -1.0f) && (x < 50.0f);
        float yc = fminf(fmaxf(y, 0.0f), 49.0f);
        float xc = fminf(fmaxf(x, 0.0f), 49.0f);
        int y0 = (int)floorf(yc), x0 = (int)floorf(xc);
        int y1 = min(y0 + 1, 49), x1 = min(x0 + 1, 49);
        float ly = yc - (float)y0, lx = xc - (float)x0;
        float vm = v ? 0.25f : 0.0f;
        sw4[tid] = make_float4((1.0f-ly)*(1.0f-lx)*vm, (1.0f-ly)*lx*vm,
                               ly*(1.0f-lx)*vm,        ly*lx*vm);
        so4[tid] = make_int4((y0*50+x0)*C_FEAT, (y0*50+x1)*C_FEAT,
                             (y1*50+x0)*C_FEAT, (y1*50+x1)*C_FEAT);
    }
    __syncthreads();

    const float* base = g_featT + ((size_t)n * HW) * C_FEAT;
    int c0 = (tid & 127) * 4;
    int ph = tid >> 7;
    for (int pos = ph; pos < 49; pos += 2) {
        float4 acc = make_float4(0.f, 0.f, 0.f, 0.f);
        #pragma unroll
        for (int s = 0; s < 4; s++) {
            float4 w = sw4[pos*4 + s];
            int4   o = so4[pos*4 + s];
            float4 f00 = *(const float4*)(base + o.x + c0);
            float4 f01 = *(const float4*)(base + o.y + c0);
            float4 f10 = *(const float4*)(base + o.z + c0);
            float4 f11 = *(const float4*)(base + o.w + c0);
            acc.x += f00.x*w.x + f01.x*w.y + f10.x*w.z + f11.x*w.w;
            acc.y += f00.y*w.x + f01.y*w.y + f10.y*w.z + f11.y*w.w;
            acc.z += f00.z*w.x + f01.z*w.y + f10.z*w.z + f11.z*w.w;
            acc.w += f00.w*w.x + f01.w*w.y + f10.w*w.z + f11.w*w.w;
        }
        split_store4(acc.x, acc.y, acc.z, acc.w,
                     (size_t)r * D_FEAT + (size_t)pos * 512 + c0);
    }
}

// ---------------- 3a) w1 -> B[n][k'=pos*512+c] bf16 hi/lo ----------------
__global__ void prep_w1(const float* __restrict__ w1) {
    __shared__ float t[32][33];
    int pos = blockIdx.x >> 4;
    int c0  = (blockIdx.x & 15) * 32;
    int n0  = blockIdx.y * 32;
    int j = threadIdx.x, i = threadIdx.y;
    t[i][j] = w1[((size_t)(c0 + i) * 49 + pos) * HIDN + n0 + j];
    __syncthreads();
    float v = t[j][i];
    __nv_bfloat16 h = __float2bfloat16(v);
    float l = v - __bfloat162float(h);
    size_t idx = (size_t)(n0 + i) * D_FEAT + (size_t)pos * 512 + c0 + j;
    g_Bhi[idx] = h;
    g_Blo[idx] = __float2bfloat16(l);
}

// ---------------- 3b) w2 -> w2T[n][k] bf16 hi/lo ----------------
__global__ void prep_w2(const float* __restrict__ w2) {
    __shared__ float t[32][33];
    int k0 = blockIdx.x * 32;
    int n0 = blockIdx.y * 32;
    int j = threadIdx.x, i = threadIdx.y;
    t[i][j] = w2[(size_t)(k0 + i) * HIDN + n0 + j];
    __syncthreads();
    float v = t[j][i];
    __nv_bfloat16 h = __float2bfloat16(v);
    float l = v - __bfloat162float(h);
    size_t idx = (size_t)(n0 + i) * HIDN + k0 + j;
    g_w2Thi[idx] = h;
    g_w2Tlo[idx] = __float2bfloat16(l);
}

// ---------------- 3c) [wc|wb] -> wcbT[n][k] bf16 hi/lo, padded to 128 cols ----
__global__ void prep_wcb(const float* __restrict__ wc, const float* __restrict__ wb,
                         const float* __restrict__ bc, const float* __restrict__ bb) {
    __shared__ float t[32][33];
    int k0 = blockIdx.x * 32;
    int n0 = blockIdx.y * 32;
    int j = threadIdx.x, i = threadIdx.y;
    int n = n0 + j, k = k0 + i;
    float v = 0.0f;
    if (n < NCLS)            v = wc[(size_t)k * NCLS + n];
    else if (n < NCLS + 84)  v = wb[(size_t)k * 84 + (n - NCLS)];
    t[i][j] = v;
    __syncthreads();
    float w = t[j][i];
    __nv_bfloat16 h = __float2bfloat16(w);
    float l = w - __bfloat162float(h);
    size_t idx = (size_t)(n0 + i) * HIDN + k0 + j;
    g_wcbhi[idx] = h;
    g_wcblo[idx] = __float2bfloat16(l);
    if (blockIdx.x == 0 && i == 0) {
        int nn = n0 + j;
        float bv = 0.0f;
        if (nn < NCLS)           bv = bc[nn];
        else if (nn < NCLS + 84) bv = bb[nn - NCLS];
        g_bcb[nn] = bv;
    }
}

// ---------------- 4) cp.async 4-stage bf16x3 GEMM (64x64 tile, 4 warps) ----------
#define SAB      40
#define MAT_B    5120
#define STAGE_B  20480
#define NSTAGE   4
#define GEMM_SMEM (NSTAGE * STAGE_B)

__global__ __launch_bounds__(128) void gemm_bf16x3(
    const __nv_bfloat16* __restrict__ Ah, const __nv_bfloat16* __restrict__ Al,
    const __nv_bfloat16* __restrict__ Bh, const __nv_bfloat16* __restrict__ Bl,
    const float* __restrict__ bias, float* __restrict__ Cf,
    __nv_bfloat16* __restrict__ Chi, __nv_bfloat16* __restrict__ Clo,
    int K, int ldc, int mode)
{
    extern __shared__ char smem[];
    const uint32_t sbase = smem_u32(smem);
    const int tid  = threadIdx.x;
    const int wid  = tid >> 5, lane = tid & 31;
    const int warp_m = wid & 1, warp_n = wid >> 1;
    const int row0 = blockIdx.y * 64;
    const int col0 = blockIdx.x * 64;
    const int NC = K >> 5;
    const size_t Kb = (size_t)K * 2;

    const int rr  = tid >> 2;
    const int seg = tid & 3;
    const char* pAhB = (const char*)Ah + (size_t)row0 * Kb;
    const char* pAlB = (const char*)Al + (size_t)row0 * Kb;
    const char* pBhB = (const char*)Bh + (size_t)col0 * Kb;
    const char* pBlB = (const char*)Bl + (size_t)col0 * Kb;
    size_t gof[2];
    uint32_t sof[2];
    #pragma unroll
    for (int q = 0; q < 2; q++) {
        gof[q] = (size_t)(q * 32 + rr) * Kb + (size_t)seg * 16;
        sof[q] = (uint32_t)((q * 32 + rr) * 80 + seg * 16);
    }

    const uint32_t aAddr = sbase +
        (uint32_t)(((warp_m * 32 + (lane & 15)) * SAB + ((lane >> 4) << 3)) * 2);
    const uint32_t bAddr = sbase + 2 * MAT_B +
        (uint32_t)(((warp_n * 32 + (lane & 7) + (((lane >> 4) & 1) << 3)) * SAB
                    + (((lane >> 3) & 1) << 3)) * 2);

    float acc[2][4][4];
    #pragma unroll
    for (int mt = 0; mt < 2; mt++)
        #pragma unroll
        for (int nt = 0; nt < 4; nt++)
            #pragma unroll
            for (int q = 0; q < 4; q++) acc[mt][nt][q] = 0.0f;

    #pragma unroll
    for (int p = 0; p < 3; p++) {
        if (p < NC) {
            uint32_t sd = sbase + (uint32_t)p * STAGE_B;
            size_t gk = (size_t)p * 64;
            #pragma unroll
            for (int q = 0; q < 2; q++) {
                CP16(sd +             sof[q], pAhB + gof[q] + gk);
                CP16(sd +     MAT_B + sof[q], pAlB + gof[q] + gk);
                CP16(sd + 2 * MAT_B + sof[q], pBhB + gof[q] + gk);
                CP16(sd + 3 * MAT_B + sof[q], pBlB + gof[q] + gk);
            }
        }
        CP_COMMIT();
    }

    for (int c = 0; c < NC; c++) {
        CP_WAIT2();
        __syncthreads();

        if (c + 3 < NC) {
            uint32_t sd = sbase + (uint32_t)((c + 3) & 3) * STAGE_B;
            size_t gk = (size_t)(c + 3) * 64;
            #pragma unroll
            for (int q = 0; q < 2; q++) {
                CP16(sd +             sof[q], pAhB + gof[q] + gk);
                CP16(sd +     MAT_B + sof[q], pAlB + gof[q] + gk);
                CP16(sd + 2 * MAT_B + sof[q], pBhB + gof[q] + gk);
                CP16(sd + 3 * MAT_B + sof[q], pBlB + gof[q] + gk);
            }
        }
        CP_COMMIT();

        const uint32_t bufo = (uint32_t)(c & 3) * STAGE_B;
        #pragma unroll
        for (int ks = 0; ks < 2; ks++) {
            const uint32_t ko = bufo + (uint32_t)ks * 32;
            uint32_t ah[2][4], al[2][4], bh[2][4], bl[2][4];
            LDSM4(ah[0], aAddr + ko);
            LDSM4(ah[1], aAddr + ko + 1280);
            LDSM4(al[0], aAddr + ko + MAT_B);
            LDSM4(al[1], aAddr + ko + MAT_B + 1280);
            LDSM4(bh[0], bAddr + ko);
            LDSM4(bh[1], bAddr + ko + 1280);
            LDSM4(bl[0], bAddr + ko + MAT_B);
            LDSM4(bl[1], bAddr + ko + MAT_B + 1280);

            #pragma unroll
            for (int mt = 0; mt < 2; mt++)
                #pragma unroll
                for (int h = 0; h < 2; h++) {
                    MMA_BF16(acc[mt][2*h+0], ah[mt], bh[h][0], bh[h][1]);
                    MMA_BF16(acc[mt][2*h+1], ah[mt], bh[h][2], bh[h][3]);
                }
            #pragma unroll
            for (int mt = 0; mt < 2; mt++)
                #pragma unroll
                for (int h = 0; h < 2; h++) {
                    MMA_BF16(acc[mt][2*h+0], ah[mt], bl[h][0], bl[h][1]);
                    MMA_BF16(acc[mt][2*h+1], ah[mt], bl[h][2], bl[h][3]);
                }
            #pragma unroll
            for (int mt = 0; mt < 2; mt++)
                #pragma unroll
                for (int h = 0; h < 2; h++) {
                    MMA_BF16(acc[mt][2*h+0], al[mt], bh[h][0], bh[h][1]);
                    MMA_BF16(acc[mt][2*h+1], al[mt], bh[h][2], bh[h][3]);
                }
        }
    }

    #pragma unroll
    for (int mt = 0; mt < 2; mt++) {
        int row = row0 + warp_m * 32 + mt * 16 + (lane >> 2);
        #pragma unroll
        for (int nt = 0; nt < 4; nt++) {
            int col = col0 + warp_n * 32 + nt * 8 + (lane & 3) * 2;
            float b0 = bias[col], b1 = bias[col + 1];
            float v0 = acc[mt][nt][0] + b0;
            float v1 = acc[mt][nt][1] + b1;
            float v2 = acc[mt][nt][2] + b0;
            float v3 = acc[mt][nt][3] + b1;
            if (mode != 2) {
                v0 = fmaxf(v0, 0.f); v1 = fmaxf(v1, 0.f);
                v2 = fmaxf(v2, 0.f); v3 = fmaxf(v3, 0.f);
            }
            if (mode == 1) {
                __nv_bfloat16 h0 = __float2bfloat16(v0), h1 = __float2bfloat16(v1);
                __nv_bfloat16 h2 = __float2bfloat16(v2), h3 = __float2bfloat16(v3);
                __nv_bfloat16 l0 = __float2bfloat16(v0 - __bfloat162float(h0));
                __nv_bfloat16 l1 = __float2bfloat16(v1 - __bfloat162float(h1));
                __nv_bfloat16 l2 = __float2bfloat16(v2 - __bfloat162float(h2));
                __nv_bfloat16 l3 = __float2bfloat16(v3 - __bfloat162float(h3));
                size_t o1 = (size_t)row * ldc + col;
                size_t o2 = (size_t)(row + 8) * ldc + col;
                *(uint32_t*)(Chi + o1) = (uint32_t)__bfloat16_as_ushort(h0) |
                                         ((uint32_t)__bfloat16_as_ushort(h1) << 16);
                *(uint32_t*)(Clo + o1) = (uint32_t)__bfloat16_as_ushort(l0) |
                                         ((uint32_t)__bfloat16_as_ushort(l1) << 16);
                *(uint32_t*)(Chi + o2) = (uint32_t)__bfloat16_as_ushort(h2) |
                                         ((uint32_t)__bfloat16_as_ushort(h3) << 16);
                *(uint32_t*)(Clo + o2) = (uint32_t)__bfloat16_as_ushort(l2) |
                                         ((uint32_t)__bfloat16_as_ushort(l3) << 16);
            } else {
                *(float2*)(Cf + (size_t)row * ldc + col)       = make_float2(v0, v1);
                *(float2*)(Cf + (size_t)(row + 8) * ldc + col) = make_float2(v2, v3);
            }
        }
    }
}

// ---------------- 5) postheads ----------------
__global__ void postheads_kernel(const float* __restrict__ props,
                                 const void* __restrict__ imgp)
{
    int r = blockIdx.x, tid = threadIdx.x;
    __shared__ float lg[NCLS + 84];
    __shared__ float ex[NCLS];

    if (tid < NCLS + 84) lg[tid] = g_logits[r * NHEAD + tid];
    __syncthreads();

    if (tid < NCLS) {
        float m = lg[0];
        #pragma unroll
        for (int i = 1; i < NCLS; i++) m = fmaxf(m, lg[i]);
        ex[tid] = expf(lg[tid] - m);
    }
    __syncthreads();

    if (tid < NCLS) {
        float s = 0.f;
        #pragma unroll
        for (int i = 0; i < NCLS; i++) s += ex[i];
        g_scores[r * NCLS + tid] = ex[tid] / s;

        float img = read_img(imgp);
        float p0 = props[r*4+0], p1 = props[r*4+1];
        float p2 = props[r*4+2], p3 = props[r*4+3];
        float pw  = p2 - p0, ph = p3 - p1;
        float pcx = p0 + 0.5f * pw, pcy = p1 + 0.5f * ph;
        float dx = lg[NCLS + tid*4+0] / 10.0f;
        float dy = lg[NCLS + tid*4+1] / 10.0f;
        float dw = fminf(lg[NCLS + tid*4+2] / 5.0f, LOG_MAX_F);
        float dh = fminf(lg[NCLS + tid*4+3] / 5.0f, LOG_MAX_F);
        float cx = dx * pw + pcx;
        float cy = dy * ph + pcy;
        float w  = expf(dw) * pw;
        float hh = expf(dh) * ph;
        float x1 = fminf(fmaxf(cx - 0.5f*w,  0.0f), img);
        float y1 = fminf(fmaxf(cy - 0.5f*hh, 0.0f), img);
        float x2 = fminf(fmaxf(cx + 0.5f*w,  0.0f), img);
        float y2 = fminf(fmaxf(cy + 0.5f*hh, 0.0f), img);
        g_boxes4[r * NCLS + tid] = make_float4(x1, y1, x2, y2);
    }
}

// ---------------- 6) NMS ----------------
#define NMS_SMEM (CANDS * 20)
__global__ __launch_bounds__(1024) void nms_kernel(const void* __restrict__ imgp,
                                                   float* __restrict__ out)
{
    extern __shared__ char nsm[];
    float4* s_nb   = (float4*)nsm;
    float*  s_live = (float*)(nsm + CANDS * 16);

    __shared__ float wbest[32];
    __shared__ int   widx[32];
    __shared__ float selS[DETN];
    __shared__ int   selI[DETN];
    __shared__ int   wsum[32];
    __shared__ float s_best;
    __shared__ int   s_si;

    int img = blockIdx.x;
    int tid = threadIdx.x;
    int lane = tid & 31, wid = tid >> 5;
    float IMG  = read_img(imgp);
    float offs = IMG + 1.0f;

    int base = tid * 10;
    uint32_t flags = 0;
    int cnt = 0;
    #pragma unroll
    for (int j = 0; j < 10; j++) {
        int cand = base + j;
        int s = cand / 20, k = cand % 20 + 1;
        int r = img * S_PER + s;
        float sc  = g_scores[r * NCLS + k];
        float4 bx = g_boxes4[r * NCLS + k];
        bool valid = (sc > 0.05f) && (bx.z - bx.x >= 0.01f) && (bx.w - bx.y >= 0.01f);
        if (valid) { flags |= (1u << j); cnt++; }
    }
    int inc = cnt;
    #pragma unroll
    for (int o = 1; o < 32; o <<= 1) {
        int u = __shfl_up_sync(0xffffffffu, inc, o);
        if (lane >= o) inc += u;
    }
    if (lane == 31) wsum[wid] = inc;
    __syncthreads();
    if (wid == 0) {
        int v = wsum[lane];
        #pragma unroll
        for (int o = 1; o < 32; o <<= 1) {
            int u = __shfl_up_sync(0xffffffffu, v, o);
            if (lane >= o) v += u;
        }
        wsum[lane] = v;
    }
    __syncthreads();
    int off = inc - cnt + (wid ? wsum[wid - 1] : 0);
    const int V = wsum[31];

    #pragma unroll
    for (int j = 0; j < 10; j++) {
        if (flags & (1u << j)) {
            int cand = base + j;
            int s = cand / 20, k = cand % 20 + 1;
            int r = img * S_PER + s;
            float sc  = g_scores[r * NCLS + k];
            float4 bx = g_boxes4[r * NCLS + k];
            float o = (float)k * offs;
            s_live[off] = sc;
            s_nb[off]   = make_float4(bx.x + o, bx.y + o, bx.z + o, bx.w + o);
            g_map[img * CANDS + off] = cand;
            off++;
        }
    }
    __syncthreads();

    int nsel = 0;
    if (V > 0) {
        float best = -2.0f; int bidx = V;
        for (int i = tid; i < V; i += 1024) {
            float v = s_live[i];
            if (v > best) { best = v; bidx = i; }
        }
        #pragma unroll
        for (int o = 16; o; o >>= 1) {
            float ov = __shfl_down_sync(0xffffffffu, best, o);
            int   oi = __shfl_down_sync(0xffffffffu, bidx, o);
            if (ov > best || (ov == best && oi < bidx)) { best = ov; bidx = oi; }
        }
        if (lane == 0) { wbest[wid] = best; widx[wid] = bidx; }
        __syncthreads();
        if (wid == 0) {
            best = wbest[lane]; bidx = widx[lane];
            #pragma unroll
            for (int o = 16; o; o >>= 1) {
                float ov = __shfl_down_sync(0xffffffffu, best, o);
                int   oi = __shfl_down_sync(0xffffffffu, bidx, o);
                if (ov > best || (ov == best && oi < bidx)) { best = ov; bidx = oi; }
            }
            if (lane == 0) { s_best = best; s_si = bidx; }
        }
        __syncthreads();

        for (int it = 0; it < DETN; it++) {
            float curb = s_best;
            int   curi = s_si;
            if (curb <= 0.05f) break;
            if (tid == 0) { selI[it] = curi; selS[it] = curb; }
            nsel++;

            float4 nbb = s_nb[curi];
            float area_i = (nbb.z - nbb.x) * (nbb.w - nbb.y);

            float nb2 = -2.0f; int ni = V;
            for (int i = tid; i < V; i += 1024) {
                float4 nb = s_nb[i];
                float xx1 = fmaxf(nbb.x, nb.x);
                float yy1 = fmaxf(nbb.y, nb.y);
                float xx2 = fminf(nbb.z, nb.z);
                float yy2 = fminf(nbb.w, nb.w);
                float inter = fmaxf(xx2 - xx1, 0.0f) * fmaxf(yy2 - yy1, 0.0f);
                float areaj = (nb.z - nb.x) * (nb.w - nb.y);
                float iou = inter / (area_i + areaj - inter + 1e-9f);
                float lv = s_live[i];
                if (iou > 0.5f) { lv = -1.0f; s_live[i] = -1.0f; }
                if (lv > nb2) { nb2 = lv; ni = i; }
            }
            #pragma unroll
            for (int o = 16; o; o >>= 1) {
                float ov = __shfl_down_sync(0xffffffffu, nb2, o);
                int   oi = __shfl_down_sync(0xffffffffu, ni, o);
                if (ov > nb2 || (ov == nb2 && oi < ni)) { nb2 = ov; ni = oi; }
            }
            if (lane == 0) { wbest[wid] = nb2; widx[wid] = ni; }
            __syncthreads();
            if (wid == 0) {
                nb2 = wbest[lane]; ni = widx[lane];
                #pragma unroll
                for (int o = 16; o; o >>= 1) {
                    float ov = __shfl_down_sync(0xffffffffu, nb2, o);
                    int   oi = __shfl_down_sync(0xffffffffu, ni, o);
                    if (ov > nb2 || (ov == nb2 && oi < ni)) { nb2 = ov; ni = oi; }
                }
                if (lane == 0) { s_best = nb2; s_si = ni; }
            }
            __syncthreads();
        }
    }

    if (tid < DETN) {
        float* ob = out + ((size_t)img * DETN + tid) * 4;
        if (tid < nsel) {
            int orig = g_map[img * CANDS + selI[tid]];
            float s = selS[tid];
            int k = orig % 20 + 1;
            int r = img * S_PER + (orig / 20);
            float4 bx = g_boxes4[r * NCLS + k];
            ob[0] = bx.x; ob[1] = bx.y; ob[2] = bx.z; ob[3] = bx.w;
            out[NIMG*DETN*4 + img*DETN + tid]             = s;
            out[NIMG*DETN*4 + NIMG*DETN + img*DETN + tid] = (float)k;
        } else {
            ob[0] = 0.f; ob[1] = 0.f; ob[2] = 0.f; ob[3] = 0.f;
            out[NIMG*DETN*4 + img*DETN + tid]             = 0.f;
            out[NIMG*DETN*4 + NIMG*DETN + img*DETN + tid] = 0.f;
        }
    }
}

// ---------------- launch ----------------
extern "C" void kernel_launch(void* const* d_in, const int* in_sizes, int n_in,
                              void* d_out, int out_size)
{
    const float* features  = (const float*)d_in[0];
    const float* proposals = (const float*)d_in[1];
    const float* w1 = (const float*)d_in[2];
    const float* b1 = (const float*)d_in[3];
    const float* w2 = (const float*)d_in[4];
    const float* b2 = (const float*)d_in[5];
    const float* wc = (const float*)d_in[6];
    const float* bc = (const float*)d_in[7];
    const float* wb = (const float*)d_in[8];
    const float* bb = (const float*)d_in[9];
    const void*  imgp = d_in[10];
    float* out = (float*)d_out;

    void *pAhi, *pAlo, *pBhi, *pBlo, *ph1hi, *ph1lo, *pw2hi, *pw2lo;
    void *ph2hi, *ph2lo, *pwcbhi, *pwcblo, *pbcb, *plogits;
    cudaGetSymbolAddress(&pAhi,  g_Ahi);
    cudaGetSymbolAddress(&pAlo,  g_Alo);
    cudaGetSymbolAddress(&pBhi,  g_Bhi);
    cudaGetSymbolAddress(&pBlo,  g_Blo);
    cudaGetSymbolAddress(&ph1hi, g_h1hi);
    cudaGetSymbolAddress(&ph1lo, g_h1lo);
    cudaGetSymbolAddress(&pw2hi, g_w2Thi);
    cudaGetSymbolAddress(&pw2lo, g_w2Tlo);
    cudaGetSymbolAddress(&ph2hi, g_h2hi);
    cudaGetSymbolAddress(&ph2lo, g_h2lo);
    cudaGetSymbolAddress(&pwcbhi, g_wcbhi);
    cudaGetSymbolAddress(&pwcblo, g_wcblo);
    cudaGetSymbolAddress(&pbcb,  g_bcb);
    cudaGetSymbolAddress(&plogits, g_logits);

    cudaFuncSetAttribute(gemm_bf16x3, cudaFuncAttributeMaxDynamicSharedMemorySize, GEMM_SMEM);
    cudaFuncSetAttribute(nms_kernel,  cudaFuncAttributeMaxDynamicSharedMemorySize, NMS_SMEM);

    static cudaStream_t s1 = nullptr;
    static cudaEvent_t evRoot = nullptr, evT = nullptr, evP1 = nullptr,
                       evRoiB = nullptr, evP2 = nullptr;
    if (s1 == nullptr) {
        cudaStreamCreateWithFlags(&s1, cudaStreamNonBlocking);
        cudaEventCreateWithFlags(&evRoot, cudaEventDisableTiming);
        cudaEventCreateWithFlags(&evT,    cudaEventDisableTiming);
        cudaEventCreateWithFlags(&evP1,   cudaEventDisableTiming);
        cudaEventCreateWithFlags(&evRoiB, cudaEventDisableTiming);
        cudaEventCreateWithFlags(&evP2,   cudaEventDisableTiming);
    }

    const __nv_bfloat16* Ahi = (const __nv_bfloat16*)pAhi;
    const __nv_bfloat16* Alo = (const __nv_bfloat16*)pAlo;
    __nv_bfloat16* h1hi = (__nv_bfloat16*)ph1hi;
    __nv_bfloat16* h1lo = (__nv_bfloat16*)ph1lo;

    // s1: prep_w1 first (needed by GEMM1a), then roiB after transpose, then other preps
    cudaEventRecord(evRoot, 0);
    cudaStreamWaitEvent(s1, evRoot, 0);
    prep_w1<<<dim3(49 * 16, 32), dim3(32, 32), 0, s1>>>(w1);
    cudaEventRecord(evP1, s1);

    // main: transpose, then roiA
    transpose_feat<<<dim3(79, 16, NIMG), dim3(32, 32)>>>(features);
    cudaEventRecord(evT, 0);
    roi_align2<<<S_PER, 256>>>(proposals, 0);

    // s1: roiB runs concurrently with GEMM1a
    cudaStreamWaitEvent(s1, evT, 0);
    roi_align2<<<S_PER, 256, 0, s1>>>(proposals, S_PER);
    cudaEventRecord(evRoiB, s1);
    prep_w2<<<dim3(32, 32), dim3(32, 32), 0, s1>>>(w2);
    prep_wcb<<<dim3(32, 4), dim3(32, 32), 0, s1>>>(wc, wb, bc, bb);
    cudaEventRecord(evP2, s1);

    // main: GEMM1a on rows 0-511 (needs roiA + prep_w1)
    cudaStreamWaitEvent(0, evP1, 0);
    gemm_bf16x3<<<dim3(HIDN/64, S_PER/64), 128, GEMM_SMEM>>>(
        Ahi, Alo,
        (const __nv_bfloat16*)pBhi, (const __nv_bfloat16*)pBlo,
        b1, nullptr, h1hi, h1lo, D_FEAT, HIDN, 1);

    // GEMM1b on rows 512-1023 (needs roiB)
    cudaStreamWaitEvent(0, evRoiB, 0);
    gemm_bf16x3<<<dim3(HIDN/64, S_PER/64), 128, GEMM_SMEM>>>(
        Ahi + (size_t)S_PER * D_FEAT, Alo + (size_t)S_PER * D_FEAT,
        (const __nv_bfloat16*)pBhi, (const __nv_bfloat16*)pBlo,
        b1, nullptr, h1hi + (size_t)S_PER * HIDN, h1lo + (size_t)S_PER * HIDN,
        D_FEAT, HIDN, 1);

    // GEMM2 (needs all h1 + prep_w2/prep_wcb)
    cudaStreamWaitEvent(0, evP2, 0);
    gemm_bf16x3<<<dim3(HIDN/64, R_TOT/64), 128, GEMM_SMEM>>>(
        (const __nv_bfloat16*)ph1hi, (const __nv_bfloat16*)ph1lo,
        (const __nv_bfloat16*)pw2hi, (const __nv_bfloat16*)pw2lo,
        b2, nullptr, (__nv_bfloat16*)ph2hi, (__nv_bfloat16*)ph2lo, HIDN, HIDN, 1);

    gemm_bf16x3<<<dim3(NHEAD/64, R_TOT/64), 128, GEMM_SMEM>>>(
        (const __nv_bfloat16*)ph2hi, (const __nv_bfloat16*)ph2lo,
        (const __nv_bfloat16*)pwcbhi, (const __nv_bfloat16*)pwcblo,
        (const float*)pbcb, (float*)plogits, nullptr, nullptr, HIDN, NHEAD, 2);

    postheads_kernel<<<R_TOT, 128>>>(proposals, imgp);
    nms_kernel<<<NIMG, 1024, NMS_SMEM>>>(imgp, out);
}

// round 14
// speedup vs baseline: 1.2822x; 1.2822x over previous
#include <cuda_runtime.h>
#include <cuda_bf16.h>
#include <math.h>
#include <cstdint>

// ---------------- problem constants ----------------
#define NIMG   2
#define S_PER  512
#define R_TOT  1024
#define C_FEAT 512
#define HW     2500
#define D_FEAT 25088
#define HIDN   1024
#define NCLS   21
#define DETN   100
#define CANDS  10240
#define NHEAD  128          // padded head output cols (105 used)
#define LOG_MAX_F 4.135166556742356f

// ---------------- scratch ----------------
__device__ float          g_featT[NIMG * HW * C_FEAT];
__device__ __nv_bfloat16  g_Ahi[(size_t)R_TOT * D_FEAT];
__device__ __nv_bfloat16  g_Alo[(size_t)R_TOT * D_FEAT];
__device__ __nv_bfloat16  g_Bhi[(size_t)HIDN * D_FEAT];
__device__ __nv_bfloat16  g_Blo[(size_t)HIDN * D_FEAT];
__device__ __nv_bfloat16  g_h1hi[R_TOT * HIDN];
__device__ __nv_bfloat16  g_h1lo[R_TOT * HIDN];
__device__ __nv_bfloat16  g_w2Thi[HIDN * HIDN];
__device__ __nv_bfloat16  g_w2Tlo[HIDN * HIDN];
__device__ __nv_bfloat16  g_h2hi[R_TOT * HIDN];
__device__ __nv_bfloat16  g_h2lo[R_TOT * HIDN];
__device__ __nv_bfloat16  g_wcbhi[NHEAD * HIDN];
__device__ __nv_bfloat16  g_wcblo[NHEAD * HIDN];
__device__ float          g_bcb[NHEAD];
__device__ float          g_logits[R_TOT * NHEAD];
__device__ float          g_scores[R_TOT * NCLS];
__device__ float4         g_boxes4[R_TOT * NCLS];
__device__ int            g_map[NIMG * CANDS];

// ---------------- helpers ----------------
__device__ __forceinline__ uint32_t smem_u32(const void* p) {
    uint32_t a;
    asm("{ .reg .u64 t; cvta.to.shared.u64 t, %1; cvt.u32.u64 %0, t; }" : "=r"(a) : "l"(p));
    return a;
}
__device__ __forceinline__ float read_img(const void* p) {
    int iv = *(const int*)p;
    if (iv > 0 && iv < 1000000) return (float)iv;
    float fv = *(const float*)p;
    if (fv >= 1.0f && fv <= 1.0e6f) return fv;
    double dv = *(const double*)p;
    return (float)dv;
}

#define LDSM4(r, a) \
    asm volatile("ldmatrix.sync.aligned.m8n8.x4.shared.b16 {%0,%1,%2,%3}, [%4];" \
        : "=r"((r)[0]), "=r"((r)[1]), "=r"((r)[2]), "=r"((r)[3]) : "r"(a))

#define MMA_BF16(c, a, b0, b1) \
    asm volatile("mma.sync.aligned.m16n8k16.row.col.f32.bf16.bf16.f32 " \
        "{%0,%1,%2,%3},{%4,%5,%6,%7},{%8,%9},{%0,%1,%2,%3};" \
        : "+f"((c)[0]), "+f"((c)[1]), "+f"((c)[2]), "+f"((c)[3]) \
        : "r"((a)[0]), "r"((a)[1]), "r"((a)[2]), "r"((a)[3]), "r"(b0), "r"(b1))

#define CP16(dst, src) \
    asm volatile("cp.async.cg.shared.global [%0], [%1], 16;" :: "r"(dst), "l"(src))
#define CP_COMMIT() asm volatile("cp.async.commit_group;" ::: "memory")
#define CP_WAIT2()  asm volatile("cp.async.wait_group 2;" ::: "memory")

// ---------------- 1) transpose features [N,C,H,W] -> [N,H,W,C] ----------------
__global__ void transpose_feat(const float* __restrict__ in) {
    __shared__ float tile[32][33];
    int n  = blockIdx.z;
    int p0 = blockIdx.x * 32;
    int c0 = blockIdx.y * 32;
    int tx = threadIdx.x, ty = threadIdx.y;
    int p = p0 + tx, c = c0 + ty;
    if (p < HW) tile[ty][tx] = in[((size_t)(n * C_FEAT + c)) * HW + p];
    __syncthreads();
    p = p0 + ty; c = c0 + tx;
    if (p < HW) g_featT[((size_t)(n * HW + p)) * C_FEAT + c] = tile[tx][ty];
}

// ---------------- 2) ROI align v2: one block per roi ------
__device__ __forceinline__ void split_store4(float v0, float v1, float v2, float v3, size_t base) {
    __nv_bfloat16 h0 = __float2bfloat16(v0), h1 = __float2bfloat16(v1),
                  h2 = __float2bfloat16(v2), h3 = __float2bfloat16(v3);
    float l0 = v0 - __bfloat162float(h0), l1 = v1 - __bfloat162float(h1),
          l2 = v2 - __bfloat162float(h2), l3 = v3 - __bfloat162float(h3);
    __nv_bfloat16 g0 = __float2bfloat16(l0), g1 = __float2bfloat16(l1),
                  g2 = __float2bfloat16(l2), g3 = __float2bfloat16(l3);
    uint2 uh, ul;
    uh.x = (uint32_t)__bfloat16_as_ushort(h0) | ((uint32_t)__bfloat16_as_ushort(h1) << 16);
    uh.y = (uint32_t)__bfloat16_as_ushort(h2) | ((uint32_t)__bfloat16_as_ushort(h3) << 16);
    ul.x = (uint32_t)__bfloat16_as_ushort(g0) | ((uint32_t)__bfloat16_as_ushort(g1) << 16);
    ul.y = (uint32_t)__bfloat16_as_ushort(g2) | ((uint32_t)__bfloat16_as_ushort(g3) << 16);
    *(uint2*)(g_Ahi + base) = uh;
    *(uint2*)(g_Alo + base) = ul;
}

__global__ __launch_bounds__(256) void roi_align2(const float* __restrict__ props) {
    __shared__ float4 sw4[196];
    __shared__ int4   so4[196];
    int r   = blockIdx.x;
    int n   = r >> 9;
    int tid = threadIdx.x;

    const float SCALE = 1.0f / 16.0f;
    float b0 = props[r*4+0] * SCALE;
    float b1 = props[r*4+1] * SCALE;
    float b2 = props[r*4+2] * SCALE;
    float b3 = props[r*4+3] * SCALE;
    float rw = fmaxf(b2 - b0, 1.0f);
    float rh = fmaxf(b3 - b1, 1.0f);
    float bw = rw * (1.0f / 7.0f);
    float bh = rh * (1.0f / 7.0f);

    if (tid < 196) {
        int pos = tid >> 2;
        int samp = tid & 3;
        int oy = pos / 7, ox = pos % 7;
        int sy = samp >> 1, sx = samp & 1;
        float gy = (float)oy + (sy ? 0.75f : 0.25f);
        float gx = (float)ox + (sx ? 0.75f : 0.25f);
        float y = b1 + gy * bh;
        float x = b0 + gx * bw;
        bool v = (y > -1.0f) && (y < 50.0f) && (x > -1.0f) && (x < 50.0f);
        float yc = fminf(fmaxf(y, 0.0f), 49.0f);
        float xc = fminf(fmaxf(x, 0.0f), 49.0f);
        int y0 = (int)floorf(yc), x0 = (int)floorf(xc);
        int y1 = min(y0 + 1, 49), x1 = min(x0 + 1, 49);
        float ly = yc - (float)y0, lx = xc - (float)x0;
        float vm = v ? 0.25f : 0.0f;
        sw4[tid] = make_float4((1.0f-ly)*(1.0f-lx)*vm, (1.0f-ly)*lx*vm,
                               ly*(1.0f-lx)*vm,        ly*lx*vm);
        so4[tid] = make_int4((y0*50+x0)*C_FEAT, (y0*50+x1)*C_FEAT,
                             (y1*50+x0)*C_FEAT, (y1*50+x1)*C_FEAT);
    }
    __syncthreads();

    const float* base = g_featT + ((size_t)n * HW) * C_FEAT;
    int c0 = (tid & 127) * 4;
    int ph = tid >> 7;
    for (int pos = ph; pos < 49; pos += 2) {
        float4 acc = make_float4(0.f, 0.f, 0.f, 0.f);
        #pragma unroll
        for (int s = 0; s < 4; s++) {
            float4 w = sw4[pos*4 + s];
            int4   o = so4[pos*4 + s];
            float4 f00 = *(const float4*)(base + o.x + c0);
            float4 f01 = *(const float4*)(base + o.y + c0);
            float4 f10 = *(const float4*)(base + o.z + c0);
            float4 f11 = *(const float4*)(base + o.w + c0);
            acc.x += f00.x*w.x + f01.x*w.y + f10.x*w.z + f11.x*w.w;
            acc.y += f00.y*w.x + f01.y*w.y + f10.y*w.z + f11.y*w.w;
            acc.z += f00.z*w.x + f01.z*w.y + f10.z*w.z + f11.z*w.w;
            acc.w += f00.w*w.x + f01.w*w.y + f10.w*w.z + f11.w*w.w;
        }
        split_store4(acc.x, acc.y, acc.z, acc.w,
                     (size_t)r * D_FEAT + (size_t)pos * 512 + c0);
    }
}

// ---------------- 3a) w1 -> B[n][k'=pos*512+c] bf16 hi/lo ----------------
__global__ void prep_w1(const float* __restrict__ w1) {
    __shared__ float t[32][33];
    int pos = blockIdx.x >> 4;
    int c0  = (blockIdx.x & 15) * 32;
    int n0  = blockIdx.y * 32;
    int j = threadIdx.x, i = threadIdx.y;
    t[i][j] = w1[((size_t)(c0 + i) * 49 + pos) * HIDN + n0 + j];
    __syncthreads();
    float v = t[j][i];
    __nv_bfloat16 h = __float2bfloat16(v);
    float l = v - __bfloat162float(h);
    size_t idx = (size_t)(n0 + i) * D_FEAT + (size_t)pos * 512 + c0 + j;
    g_Bhi[idx] = h;
    g_Blo[idx] = __float2bfloat16(l);
}

// ---------------- 3b) w2 -> w2T[n][k] bf16 hi/lo ----------------
__global__ void prep_w2(const float* __restrict__ w2) {
    __shared__ float t[32][33];
    int k0 = blockIdx.x * 32;
    int n0 = blockIdx.y * 32;
    int j = threadIdx.x, i = threadIdx.y;
    t[i][j] = w2[(size_t)(k0 + i) * HIDN + n0 + j];
    __syncthreads();
    float v = t[j][i];
    __nv_bfloat16 h = __float2bfloat16(v);
    float l = v - __bfloat162float(h);
    size_t idx = (size_t)(n0 + i) * HIDN + k0 + j;
    g_w2Thi[idx] = h;
    g_w2Tlo[idx] = __float2bfloat16(l);
}

// ---------------- 3c) [wc|wb] -> wcbT[n][k] bf16 hi/lo, padded to 128 cols ----
__global__ void prep_wcb(const float* __restrict__ wc, const float* __restrict__ wb,
                         const float* __restrict__ bc, const float* __restrict__ bb) {
    __shared__ float t[32][33];
    int k0 = blockIdx.x * 32;
    int n0 = blockIdx.y * 32;
    int j = threadIdx.x, i = threadIdx.y;
    int n = n0 + j, k = k0 + i;
    float v = 0.0f;
    if (n < NCLS)            v = wc[(size_t)k * NCLS + n];
    else if (n < NCLS + 84)  v = wb[(size_t)k * 84 + (n - NCLS)];
    t[i][j] = v;
    __syncthreads();
    float w = t[j][i];
    __nv_bfloat16 h = __float2bfloat16(w);
    float l = w - __bfloat162float(h);
    size_t idx = (size_t)(n0 + i) * HIDN + k0 + j;
    g_wcbhi[idx] = h;
    g_wcblo[idx] = __float2bfloat16(l);
    if (blockIdx.x == 0 && i == 0) {
        int nn = n0 + j;
        float bv = 0.0f;
        if (nn < NCLS)           bv = bc[nn];
        else if (nn < NCLS + 84) bv = bb[nn - NCLS];
        g_bcb[nn] = bv;
    }
}

// ---------------- 4) cp.async 4-stage bf16x3 GEMM (64x64 tile, 4 warps) ----------
// mode 0: relu + fp32 ; mode 1: relu + split bf16 ; mode 2: plain fp32 (no relu)
#define SAB      40
#define MAT_B    5120
#define STAGE_B  20480
#define NSTAGE   4
#define GEMM_SMEM (NSTAGE * STAGE_B)   // 81920

__global__ __launch_bounds__(128) void gemm_bf16x3(
    const __nv_bfloat16* __restrict__ Ah, const __nv_bfloat16* __restrict__ Al,
    const __nv_bfloat16* __restrict__ Bh, const __nv_bfloat16* __restrict__ Bl,
    const float* __restrict__ bias, float* __restrict__ Cf,
    __nv_bfloat16* __restrict__ Chi, __nv_bfloat16* __restrict__ Clo,
    int K, int ldc, int mode)
{
    extern __shared__ char smem[];
    const uint32_t sbase = smem_u32(smem);
    const int tid  = threadIdx.x;
    const int wid  = tid >> 5, lane = tid & 31;
    const int warp_m = wid & 1, warp_n = wid >> 1;
    const int row0 = blockIdx.y * 64;
    const int col0 = blockIdx.x * 64;
    const int NC = K >> 5;
    const size_t Kb = (size_t)K * 2;

    const int rr  = tid >> 2;
    const int seg = tid & 3;
    const char* pAhB = (const char*)Ah + (size_t)row0 * Kb;
    const char* pAlB = (const char*)Al + (size_t)row0 * Kb;
    const char* pBhB = (const char*)Bh + (size_t)col0 * Kb;
    const char* pBlB = (const char*)Bl + (size_t)col0 * Kb;
    size_t gof[2];
    uint32_t sof[2];
    #pragma unroll
    for (int q = 0; q < 2; q++) {
        gof[q] = (size_t)(q * 32 + rr) * Kb + (size_t)seg * 16;
        sof[q] = (uint32_t)((q * 32 + rr) * 80 + seg * 16);
    }

    const uint32_t aAddr = sbase +
        (uint32_t)(((warp_m * 32 + (lane & 15)) * SAB + ((lane >> 4) << 3)) * 2);
    const uint32_t bAddr = sbase + 2 * MAT_B +
        (uint32_t)(((warp_n * 32 + (lane & 7) + (((lane >> 4) & 1) << 3)) * SAB
                    + (((lane >> 3) & 1) << 3)) * 2);

    float acc[2][4][4];
    #pragma unroll
    for (int mt = 0; mt < 2; mt++)
        #pragma unroll
        for (int nt = 0; nt < 4; nt++)
            #pragma unroll
            for (int q = 0; q < 4; q++) acc[mt][nt][q] = 0.0f;

    #pragma unroll
    for (int p = 0; p < 3; p++) {
        if (p < NC) {
            uint32_t sd = sbase + (uint32_t)p * STAGE_B;
            size_t gk = (size_t)p * 64;
            #pragma unroll
            for (int q = 0; q < 2; q++) {
                CP16(sd +             sof[q], pAhB + gof[q] + gk);
                CP16(sd +     MAT_B + sof[q], pAlB + gof[q] + gk);
                CP16(sd + 2 * MAT_B + sof[q], pBhB + gof[q] + gk);
                CP16(sd + 3 * MAT_B + sof[q], pBlB + gof[q] + gk);
            }
        }
        CP_COMMIT();
    }

    for (int c = 0; c < NC; c++) {
        CP_WAIT2();
        __syncthreads();

        if (c + 3 < NC) {
            uint32_t sd = sbase + (uint32_t)((c + 3) & 3) * STAGE_B;
            size_t gk = (size_t)(c + 3) * 64;
            #pragma unroll
            for (int q = 0; q < 2; q++) {
                CP16(sd +             sof[q], pAhB + gof[q] + gk);
                CP16(sd +     MAT_B + sof[q], pAlB + gof[q] + gk);
                CP16(sd + 2 * MAT_B + sof[q], pBhB + gof[q] + gk);
                CP16(sd + 3 * MAT_B + sof[q], pBlB + gof[q] + gk);
            }
        }
        CP_COMMIT();

        const uint32_t bufo = (uint32_t)(c & 3) * STAGE_B;
        #pragma unroll
        for (int ks = 0; ks < 2; ks++) {
            const uint32_t ko = bufo + (uint32_t)ks * 32;
            uint32_t ah[2][4], al[2][4], bh[2][4], bl[2][4];
            LDSM4(ah[0], aAddr + ko);
            LDSM4(ah[1], aAddr + ko + 1280);
            LDSM4(al[0], aAddr + ko + MAT_B);
            LDSM4(al[1], aAddr + ko + MAT_B + 1280);
            LDSM4(bh[0], bAddr + ko);
            LDSM4(bh[1], bAddr + ko + 1280);
            LDSM4(bl[0], bAddr + ko + MAT_B);
            LDSM4(bl[1], bAddr + ko + MAT_B + 1280);

            #pragma unroll
            for (int mt = 0; mt < 2; mt++)
                #pragma unroll
                for (int h = 0; h < 2; h++) {
                    MMA_BF16(acc[mt][2*h+0], ah[mt], bh[h][0], bh[h][1]);
                    MMA_BF16(acc[mt][2*h+1], ah[mt], bh[h][2], bh[h][3]);
                }
            #pragma unroll
            for (int mt = 0; mt < 2; mt++)
                #pragma unroll
                for (int h = 0; h < 2; h++) {
                    MMA_BF16(acc[mt][2*h+0], ah[mt], bl[h][0], bl[h][1]);
                    MMA_BF16(acc[mt][2*h+1], ah[mt], bl[h][2], bl[h][3]);
                }
            #pragma unroll
            for (int mt = 0; mt < 2; mt++)
                #pragma unroll
                for (int h = 0; h < 2; h++) {
                    MMA_BF16(acc[mt][2*h+0], al[mt], bh[h][0], bh[h][1]);
                    MMA_BF16(acc[mt][2*h+1], al[mt], bh[h][2], bh[h][3]);
                }
        }
    }

    #pragma unroll
    for (int mt = 0; mt < 2; mt++) {
        int row = row0 + warp_m * 32 + mt * 16 + (lane >> 2);
        #pragma unroll
        for (int nt = 0; nt < 4; nt++) {
            int col = col0 + warp_n * 32 + nt * 8 + (lane & 3) * 2;
            float b0 = bias[col], b1 = bias[col + 1];
            float v0 = acc[mt][nt][0] + b0;
            float v1 = acc[mt][nt][1] + b1;
            float v2 = acc[mt][nt][2] + b0;
            float v3 = acc[mt][nt][3] + b1;
            if (mode != 2) {
                v0 = fmaxf(v0, 0.f); v1 = fmaxf(v1, 0.f);
                v2 = fmaxf(v2, 0.f); v3 = fmaxf(v3, 0.f);
            }
            if (mode == 1) {
                __nv_bfloat16 h0 = __float2bfloat16(v0), h1 = __float2bfloat16(v1);
                __nv_bfloat16 h2 = __float2bfloat16(v2), h3 = __float2bfloat16(v3);
                __nv_bfloat16 l0 = __float2bfloat16(v0 - __bfloat162float(h0));
                __nv_bfloat16 l1 = __float2bfloat16(v1 - __bfloat162float(h1));
                __nv_bfloat16 l2 = __float2bfloat16(v2 - __bfloat162float(h2));
                __nv_bfloat16 l3 = __float2bfloat16(v3 - __bfloat162float(h3));
                size_t o1 = (size_t)row * ldc + col;
                size_t o2 = (size_t)(row + 8) * ldc + col;
                *(uint32_t*)(Chi + o1) = (uint32_t)__bfloat16_as_ushort(h0) |
                                         ((uint32_t)__bfloat16_as_ushort(h1) << 16);
                *(uint32_t*)(Clo + o1) = (uint32_t)__bfloat16_as_ushort(l0) |
                                         ((uint32_t)__bfloat16_as_ushort(l1) << 16);
                *(uint32_t*)(Chi + o2) = (uint32_t)__bfloat16_as_ushort(h2) |
                                         ((uint32_t)__bfloat16_as_ushort(h3) << 16);
                *(uint32_t*)(Clo + o2) = (uint32_t)__bfloat16_as_ushort(l2) |
                                         ((uint32_t)__bfloat16_as_ushort(l3) << 16);
            } else {
                *(float2*)(Cf + (size_t)row * ldc + col)       = make_float2(v0, v1);
                *(float2*)(Cf + (size_t)(row + 8) * ldc + col) = make_float2(v2, v3);
            }
        }
    }
}

// ---------------- 5) postheads: softmax + decode from precomputed logits ----
__global__ void postheads_kernel(const float* __restrict__ props,
                                 const void* __restrict__ imgp)
{
    int r = blockIdx.x, tid = threadIdx.x;
    __shared__ float lg[NCLS + 84];
    __shared__ float ex[NCLS];

    if (tid < NCLS + 84) lg[tid] = g_logits[r * NHEAD + tid];
    __syncthreads();

    if (tid < NCLS) {
        float m = lg[0];
        #pragma unroll
        for (int i = 1; i < NCLS; i++) m = fmaxf(m, lg[i]);
        ex[tid] = expf(lg[tid] - m);
    }
    __syncthreads();

    if (tid < NCLS) {
        float s = 0.f;
        #pragma unroll
        for (int i = 0; i < NCLS; i++) s += ex[i];
        g_scores[r * NCLS + tid] = ex[tid] / s;

        float img = read_img(imgp);
        float p0 = props[r*4+0], p1 = props[r*4+1];
        float p2 = props[r*4+2], p3 = props[r*4+3];
        float pw  = p2 - p0, ph = p3 - p1;
        float pcx = p0 + 0.5f * pw, pcy = p1 + 0.5f * ph;
        float dx = lg[NCLS + tid*4+0] / 10.0f;
        float dy = lg[NCLS + tid*4+1] / 10.0f;
        float dw = fminf(lg[NCLS + tid*4+2] / 5.0f, LOG_MAX_F);
        float dh = fminf(lg[NCLS + tid*4+3] / 5.0f, LOG_MAX_F);
        float cx = dx * pw + pcx;
        float cy = dy * ph + pcy;
        float w  = expf(dw) * pw;
        float hh = expf(dh) * ph;
        float x1 = fminf(fmaxf(cx - 0.5f*w,  0.0f), img);
        float y1 = fminf(fmaxf(cy - 0.5f*hh, 0.0f), img);
        float x2 = fminf(fmaxf(cx + 0.5f*w,  0.0f), img);
        float y2 = fminf(fmaxf(cy + 0.5f*hh, 0.0f), img);
        g_boxes4[r * NCLS + tid] = make_float4(x1, y1, x2, y2);
    }
}

// ---------------- 6) NMS: compaction + fused suppress/argmax + early exit ----
#define NMS_SMEM (CANDS * 20)
__global__ __launch_bounds__(1024) void nms_kernel(const void* __restrict__ imgp,
                                                   float* __restrict__ out)
{
    extern __shared__ char nsm[];
    float4* s_nb   = (float4*)nsm;
    float*  s_live = (float*)(nsm + CANDS * 16);

    __shared__ float wbest[32];
    __shared__ int   widx[32];
    __shared__ float selS[DETN];
    __shared__ int   selI[DETN];
    __shared__ int   wsum[32];
    __shared__ float s_best;
    __shared__ int   s_si;

    int img = blockIdx.x;
    int tid = threadIdx.x;
    int lane = tid & 31, wid = tid >> 5;
    float IMG  = read_img(imgp);
    float offs = IMG + 1.0f;

    int base = tid * 10;
    uint32_t flags = 0;
    int cnt = 0;
    #pragma unroll
    for (int j = 0; j < 10; j++) {
        int cand = base + j;
        int s = cand / 20, k = cand % 20 + 1;
        int r = img * S_PER + s;
        float sc  = g_scores[r * NCLS + k];
        float4 bx = g_boxes4[r * NCLS + k];
        bool valid = (sc > 0.05f) && (bx.z - bx.x >= 0.01f) && (bx.w - bx.y >= 0.01f);
        if (valid) { flags |= (1u << j); cnt++; }
    }
    int inc = cnt;
    #pragma unroll
    for (int o = 1; o < 32; o <<= 1) {
        int u = __shfl_up_sync(0xffffffffu, inc, o);
        if (lane >= o) inc += u;
    }
    if (lane == 31) wsum[wid] = inc;
    __syncthreads();
    if (wid == 0) {
        int v = wsum[lane];
        #pragma unroll
        for (int o = 1; o < 32; o <<= 1) {
            int u = __shfl_up_sync(0xffffffffu, v, o);
            if (lane >= o) v += u;
        }
        wsum[lane] = v;
    }
    __syncthreads();
    int off = inc - cnt + (wid ? wsum[wid - 1] : 0);
    const int V = wsum[31];

    #pragma unroll
    for (int j = 0; j < 10; j++) {
        if (flags & (1u << j)) {
            int cand = base + j;
            int s = cand / 20, k = cand % 20 + 1;
            int r = img * S_PER + s;
            float sc  = g_scores[r * NCLS + k];
            float4 bx = g_boxes4[r * NCLS + k];
            float o = (float)k * offs;
            s_live[off] = sc;
            s_nb[off]   = make_float4(bx.x + o, bx.y + o, bx.z + o, bx.w + o);
            g_map[img * CANDS + off] = cand;
            off++;
        }
    }
    __syncthreads();

    int nsel = 0;
    if (V > 0) {
        float best = -2.0f; int bidx = V;
        for (int i = tid; i < V; i += 1024) {
            float v = s_live[i];
            if (v > best) { best = v; bidx = i; }
        }
        #pragma unroll
        for (int o = 16; o; o >>= 1) {
            float ov = __shfl_down_sync(0xffffffffu, best, o);
            int   oi = __shfl_down_sync(0xffffffffu, bidx, o);
            if (ov > best || (ov == best && oi < bidx)) { best = ov; bidx = oi; }
        }
        if (lane == 0) { wbest[wid] = best; widx[wid] = bidx; }
        __syncthreads();
        if (wid == 0) {
            best = wbest[lane]; bidx = widx[lane];
            #pragma unroll
            for (int o = 16; o; o >>= 1) {
                float ov = __shfl_down_sync(0xffffffffu, best, o);
                int   oi = __shfl_down_sync(0xffffffffu, bidx, o);
                if (ov > best || (ov == best && oi < bidx)) { best = ov; bidx = oi; }
            }
            if (lane == 0) { s_best = best; s_si = bidx; }
        }
        __syncthreads();

        for (int it = 0; it < DETN; it++) {
            float curb = s_best;
            int   curi = s_si;
            if (curb <= 0.05f) break;
            if (tid == 0) { selI[it] = curi; selS[it] = curb; }
            nsel++;

            float4 nbb = s_nb[curi];
            float area_i = (nbb.z - nbb.x) * (nbb.w - nbb.y);

            float nb2 = -2.0f; int ni = V;
            for (int i = tid; i < V; i += 1024) {
                float4 nb = s_nb[i];
                float xx1 = fmaxf(nbb.x, nb.x);
                float yy1 = fmaxf(nbb.y, nb.y);
                float xx2 = fminf(nbb.z, nb.z);
                float yy2 = fminf(nbb.w, nb.w);
                float inter = fmaxf(xx2 - xx1, 0.0f) * fmaxf(yy2 - yy1, 0.0f);
                float areaj = (nb.z - nb.x) * (nb.w - nb.y);
                float iou = inter / (area_i + areaj - inter + 1e-9f);
                float lv = s_live[i];
                if (iou > 0.5f) { lv = -1.0f; s_live[i] = -1.0f; }
                if (lv > nb2) { nb2 = lv; ni = i; }
            }
            #pragma unroll
            for (int o = 16; o; o >>= 1) {
                float ov = __shfl_down_sync(0xffffffffu, nb2, o);
                int   oi = __shfl_down_sync(0xffffffffu, ni, o);
                if (ov > nb2 || (ov == nb2 && oi < ni)) { nb2 = ov; ni = oi; }
            }
            if (lane == 0) { wbest[wid] = nb2; widx[wid] = ni; }
            __syncthreads();
            if (wid == 0) {
                nb2 = wbest[lane]; ni = widx[lane];
                #pragma unroll
                for (int o = 16; o; o >>= 1) {
                    float ov = __shfl_down_sync(0xffffffffu, nb2, o);
                    int   oi = __shfl_down_sync(0xffffffffu, ni, o);
                    if (ov > nb2 || (ov == nb2 && oi < ni)) { nb2 = ov; ni = oi; }
                }
                if (lane == 0) { s_best = nb2; s_si = ni; }
            }
            __syncthreads();
        }
    }

    if (tid < DETN) {
        float* ob = out + ((size_t)img * DETN + tid) * 4;
        if (tid < nsel) {
            int orig = g_map[img * CANDS + selI[tid]];
            float s = selS[tid];
            int k = orig % 20 + 1;
            int r = img * S_PER + (orig / 20);
            float4 bx = g_boxes4[r * NCLS + k];
            ob[0] = bx.x; ob[1] = bx.y; ob[2] = bx.z; ob[3] = bx.w;
            out[NIMG*DETN*4 + img*DETN + tid]             = s;
            out[NIMG*DETN*4 + NIMG*DETN + img*DETN + tid] = (float)k;
        } else {
            ob[0] = 0.f; ob[1] = 0.f; ob[2] = 0.f; ob[3] = 0.f;
            out[NIMG*DETN*4 + img*DETN + tid]             = 0.f;
            out[NIMG*DETN*4 + NIMG*DETN + img*DETN + tid] = 0.f;
        }
    }
}

// ---------------- launch ----------------
extern "C" void kernel_launch(void* const* d_in, const int* in_sizes, int n_in,
                              void* d_out, int out_size)
{
    const float* features  = (const float*)d_in[0];
    const float* proposals = (const float*)d_in[1];
    const float* w1 = (const float*)d_in[2];
    const float* b1 = (const float*)d_in[3];
    const float* w2 = (const float*)d_in[4];
    const float* b2 = (const float*)d_in[5];
    const float* wc = (const float*)d_in[6];
    const float* bc = (const float*)d_in[7];
    const float* wb = (const float*)d_in[8];
    const float* bb = (const float*)d_in[9];
    const void*  imgp = d_in[10];
    float* out = (float*)d_out;

    void *pAhi, *pAlo, *pBhi, *pBlo, *ph1hi, *ph1lo, *pw2hi, *pw2lo;
    void *ph2hi, *ph2lo, *pwcbhi, *pwcblo, *pbcb, *plogits;
    cudaGetSymbolAddress(&pAhi,  g_Ahi);
    cudaGetSymbolAddress(&pAlo,  g_Alo);
    cudaGetSymbolAddress(&pBhi,  g_Bhi);
    cudaGetSymbolAddress(&pBlo,  g_Blo);
    cudaGetSymbolAddress(&ph1hi, g_h1hi);
    cudaGetSymbolAddress(&ph1lo, g_h1lo);
    cudaGetSymbolAddress(&pw2hi, g_w2Thi);
    cudaGetSymbolAddress(&pw2lo, g_w2Tlo);
    cudaGetSymbolAddress(&ph2hi, g_h2hi);
    cudaGetSymbolAddress(&ph2lo, g_h2lo);
    cudaGetSymbolAddress(&pwcbhi, g_wcbhi);
    cudaGetSymbolAddress(&pwcblo, g_wcblo);
    cudaGetSymbolAddress(&pbcb,  g_bcb);
    cudaGetSymbolAddress(&plogits, g_logits);

    cudaFuncSetAttribute(gemm_bf16x3, cudaFuncAttributeMaxDynamicSharedMemorySize, GEMM_SMEM);
    cudaFuncSetAttribute(nms_kernel,  cudaFuncAttributeMaxDynamicSharedMemorySize, NMS_SMEM);

    static cudaStream_t s1 = nullptr;
    static cudaEvent_t evRoot = nullptr, evPrep = nullptr;
    if (s1 == nullptr) {
        cudaStreamCreateWithFlags(&s1, cudaStreamNonBlocking);
        cudaEventCreateWithFlags(&evRoot, cudaEventDisableTiming);
        cudaEventCreateWithFlags(&evPrep, cudaEventDisableTiming);
    }

    cudaEventRecord(evRoot, 0);
    cudaStreamWaitEvent(s1, evRoot, 0);
    prep_w1<<<dim3(49 * 16, 32), dim3(32, 32), 0, s1>>>(w1);
    prep_w2<<<dim3(32, 32), dim3(32, 32), 0, s1>>>(w2);
    prep_wcb<<<dim3(32, 4), dim3(32, 32), 0, s1>>>(wc, wb, bc, bb);
    cudaEventRecord(evPrep, s1);

    transpose_feat<<<dim3(79, 16, NIMG), dim3(32, 32)>>>(features);
    roi_align2<<<R_TOT, 256>>>(proposals);

    cudaStreamWaitEvent(0, evPrep, 0);

    gemm_bf16x3<<<dim3(HIDN/64, R_TOT/64), 128, GEMM_SMEM>>>(
        (const __nv_bfloat16*)pAhi, (const __nv_bfloat16*)pAlo,
        (const __nv_bfloat16*)pBhi, (const __nv_bfloat16*)pBlo,
        b1, nullptr, (__nv_bfloat16*)ph1hi, (__nv_bfloat16*)ph1lo, D_FEAT, HIDN, 1);

    gemm_bf16x3<<<dim3(HIDN/64, R_TOT/64), 128, GEMM_SMEM>>>(
        (const __nv_bfloat16*)ph1hi, (const __nv_bfloat16*)ph1lo,
        (const __nv_bfloat16*)pw2hi, (const __nv_bfloat16*)pw2lo,
        b2, nullptr, (__nv_bfloat16*)ph2hi, (__nv_bfloat16*)ph2lo, HIDN, HIDN, 1);

    gemm_bf16x3<<<dim3(NHEAD/64, R_TOT/64), 128, GEMM_SMEM>>>(
        (const __nv_bfloat16*)ph2hi, (const __nv_bfloat16*)ph2lo,
        (const __nv_bfloat16*)pwcbhi, (const __nv_bfloat16*)pwcblo,
        (const float*)pbcb, (float*)plogits, nullptr, nullptr, HIDN, NHEAD, 2);

    postheads_kernel<<<R_TOT, 128>>>(proposals, imgp);
    nms_kernel<<<NIMG, 1024, NMS_SMEM>>>(imgp, out);
}